// round 11
// baseline (speedup 1.0000x reference)
#include <cuda_runtime.h>
#include <cuda_fp16.h>
#include <stdint.h>

#define ED 128
#define DHALF 64
#define TILE_M 128
#define THREADS 512
#define ROWB 272   // fp16 row stride in bytes (136 halfs) -> conflict-free ldmatrix

// ---------------- device globals ----------------
__device__ __half g_W1h[ED * ED];
__device__ int g_idx64;

// ---------------- helpers ----------------
__device__ __forceinline__ uint32_t smem_u32(const void* p) {
    uint32_t a;
    asm("{ .reg .u64 t; cvta.to.shared.u64 t, %1; cvt.u32.u64 %0, t; }" : "=r"(a) : "l"(p));
    return a;
}
__device__ __forceinline__ void ldsm_x4(uint32_t* r, uint32_t addr) {
    asm volatile("ldmatrix.sync.aligned.m8n8.x4.shared.b16 {%0,%1,%2,%3}, [%4];"
                 : "=r"(r[0]), "=r"(r[1]), "=r"(r[2]), "=r"(r[3]) : "r"(addr));
}
__device__ __forceinline__ void mma16816(float* c, const uint32_t* a, uint32_t b0, uint32_t b1) {
    asm volatile("mma.sync.aligned.m16n8k16.row.col.f32.f16.f16.f32 "
                 "{%0,%1,%2,%3}, {%4,%5,%6,%7}, {%8,%9}, {%0,%1,%2,%3};"
                 : "+f"(c[0]), "+f"(c[1]), "+f"(c[2]), "+f"(c[3])
                 : "r"(a[0]), "r"(a[1]), "r"(a[2]), "r"(a[3]), "r"(b0), "r"(b1));
}

// smem layout (bytes)
#define SM_PART 0                        // float[4][128]
#define SM_B1   2048                     // float[128]
#define SM_W2   2560                     // float[128]
#define SM_BH   3072                     // 128 rows x ROWB
#define SM_AH   (SM_BH + ED * ROWB)      // 128 rows x ROWB
#define SMEM_BYTES (SM_AH + TILE_M * ROWB)

// ---------------- prep: W1 -> fp16; sniff idx dtype ----------------
__global__ void pip_prep(const float* __restrict__ W1, const void* __restrict__ idxl,
                         long long P, long long Nnodes) {
    int i = blockIdx.x * blockDim.x + threadIdx.x;
    if (i < ED * ED) g_W1h[i] = __float2half_rn(W1[i]);
    if (blockIdx.x == 0 && threadIdx.x == 0) {
        const unsigned long long* p64 = (const unsigned long long*)idxl;
        long long n = 512;
        if (2 * n > P) n = P / 2;
        int ok = 1;
        for (long long k = 0; k < n; k++)
            if (p64[k] >= (unsigned long long)Nnodes) { ok = 0; break; }
        g_idx64 = ok;
    }
}

// ---------------- main persistent kernel ----------------
extern "C" __global__ void __launch_bounds__(THREADS, 1)
pip_main(const float* __restrict__ g1, const float* __restrict__ g2,
         const void* __restrict__ idxl, const void* __restrict__ idxr,
         const float* __restrict__ b1, const float* __restrict__ W2,
         const float* __restrict__ b2, float* __restrict__ out,
         long long P, long long Nnodes) {
    extern __shared__ char smem[];
    const uint32_t sb = smem_u32(smem);
    const int tid = threadIdx.x;
    const int wid = tid >> 5;
    const int lid = tid & 31;
    const int is64 = g_idx64;

    // ---- stage b1 / W2 / W1h(B tile, resident all kernel) ----
    for (int i = tid; i < ED; i += THREADS) {
        ((float*)(smem + SM_B1))[i] = b1[i];
        ((float*)(smem + SM_W2))[i] = W2[i];
    }
    for (int i = tid; i < ED * 32; i += THREADS) {  // uint2 = 4 halfs
        int n = i >> 5, kq = i & 31;
        *(uint2*)(smem + SM_BH + n * ROWB + kq * 8) = ((const uint2*)g_W1h)[i];
    }
    __syncthreads();

    // warp tiling: 4m x 4n, warp tile m32 x n32
    const int m0 = (wid >> 2) * 32;
    const int n0 = (wid & 3) * 32;
    const int a_row = (lid & 7) + ((lid >> 3) & 1) * 8;
    const int a_kad = ((lid >> 4) & 1) * 8;
    const int b_row = (lid & 7) + ((lid >> 4) & 1) * 8;
    const int b_kad = ((lid >> 3) & 1) * 8;

    // persistent B fragments for ks = 0..3 (loaded once; B never changes;
    // consumed with compile-time indices only)
    uint32_t bp[4][2][4];
#pragma unroll
    for (int ks = 0; ks < 4; ks++)
#pragma unroll
        for (int nq = 0; nq < 2; nq++) {
            uint32_t bo = (uint32_t)((n0 + nq * 16 + b_row) * ROWB +
                                     (ks * 16 + b_kad) * 2);
            ldsm_x4(bp[ks][nq], sb + SM_BH + bo);
        }

    // gather role (coalesced): warp w owns tile rows [8w, 8w+8).
    // lanes 0-15 read left table, 16-31 right table; lane j = float4 j of the row.
    const int sslot = (lid >> 4) & 1;
    const int j = lid & 15;
    const void* isrc = sslot ? idxr : idxl;
    const float* gsrc = sslot ? g2 : g1;

    const float b2v = b2[0];
    const long long nTiles = (P + TILE_M - 1) / TILE_M;
    const long long grid = gridDim.x;
    float* part = (float*)(smem + SM_PART);
    const float* s_b1 = (const float*)(smem + SM_B1);
    const float* s_w2 = (const float*)(smem + SM_W2);

    long long t = blockIdx.x;
    uint2 v[8];   // gathered row fragment, already fp16x4

    // ---- prologue: gather tile t (convert to fp16 at load) ----
    if (t < nTiles) {
#pragma unroll
        for (int i = 0; i < 8; i++) {
            long long p = t * TILE_M + wid * 8 + i;
            if (p >= P) p = 0;
            long long gi = is64 ? ((const long long*)isrc)[p]
                                : (long long)((const int*)isrc)[p];
            float4 f = ((const float4*)(gsrc + gi * DHALF))[j];
            __half2 h01 = __floats2half2_rn(f.x, f.y);
            __half2 h23 = __floats2half2_rn(f.z, f.w);
            v[i].x = *(uint32_t*)&h01;
            v[i].y = *(uint32_t*)&h23;
        }
    }

    for (; t < nTiles; t += grid) {
        const long long base = t * TILE_M;

        // ---- STS: fp16 A tile (two contiguous 128B segments per instr) ----
        {
            const uint32_t abase = (uint32_t)(wid * 8 * ROWB + sslot * 128 + j * 8);
#pragma unroll
            for (int i = 0; i < 8; i++)
                *(uint2*)(smem + SM_AH + abase + i * ROWB) = v[i];
        }
        __syncthreads();  // A(t) ready

        // ---- issue next-tile gather (hidden under GEMM) ----
        const long long tn = t + grid;
        if (tn < nTiles) {
#pragma unroll
            for (int i = 0; i < 8; i++) {
                long long p = tn * TILE_M + wid * 8 + i;
                if (p >= P) p = 0;
                long long gi = is64 ? ((const long long*)isrc)[p]
                                    : (long long)((const int*)isrc)[p];
                float4 f = ((const float4*)(gsrc + gi * DHALF))[j];
                __half2 h01 = __floats2half2_rn(f.x, f.y);
                __half2 h23 = __floats2half2_rn(f.z, f.w);
                v[i].x = *(uint32_t*)&h01;
                v[i].y = *(uint32_t*)&h23;
            }
        }

        // ---- GEMM: c = A * W1h^T ----
        float c[2][4][4];
#pragma unroll
        for (int mt = 0; mt < 2; mt++)
#pragma unroll
            for (int nf = 0; nf < 4; nf++)
#pragma unroll
                for (int jj = 0; jj < 4; jj++) c[mt][nf][jj] = 0.0f;

        // ks 0..3: A-ldsm only, B from persistent registers (compile-time idx)
#pragma unroll
        for (int ks = 0; ks < 4; ks++) {
            uint32_t ah[2][4];
#pragma unroll
            for (int mt = 0; mt < 2; mt++) {
                uint32_t ao = (uint32_t)((m0 + mt * 16 + a_row) * ROWB +
                                         (ks * 16 + a_kad) * 2);
                ldsm_x4(ah[mt], sb + SM_AH + ao);
            }
#pragma unroll
            for (int mt = 0; mt < 2; mt++)
#pragma unroll
                for (int nq = 0; nq < 2; nq++)
#pragma unroll
                    for (int f = 0; f < 2; f++)
                        mma16816(c[mt][nq * 2 + f], ah[mt],
                                 bp[ks][nq][2 * f], bp[ks][nq][2 * f + 1]);
        }

        // ks 4..7: identical to R6 body (A + B ldsm then mma)
#pragma unroll
        for (int ks = 4; ks < 8; ks++) {
            uint32_t ah[2][4], bh[2][4];
#pragma unroll
            for (int mt = 0; mt < 2; mt++) {
                uint32_t ao = (uint32_t)((m0 + mt * 16 + a_row) * ROWB +
                                         (ks * 16 + a_kad) * 2);
                ldsm_x4(ah[mt], sb + SM_AH + ao);
            }
#pragma unroll
            for (int nq = 0; nq < 2; nq++) {
                uint32_t bo = (uint32_t)((n0 + nq * 16 + b_row) * ROWB +
                                         (ks * 16 + b_kad) * 2);
                ldsm_x4(bh[nq], sb + SM_BH + bo);
            }
#pragma unroll
            for (int mt = 0; mt < 2; mt++)
#pragma unroll
                for (int nq = 0; nq < 2; nq++)
#pragma unroll
                    for (int f = 0; f < 2; f++)
                        mma16816(c[mt][nq * 2 + f], ah[mt],
                                 bh[nq][2 * f], bh[nq][2 * f + 1]);
        }

        // ---- epilogue: bias + relu + dot(W2) partials ----
        {
            const int tq = lid & 3;
            const int q = lid >> 2;
            const int wn = wid & 3;
#pragma unroll
            for (int mt = 0; mt < 2; mt++) {
                float s0 = 0.0f, s1 = 0.0f;
#pragma unroll
                for (int nf = 0; nf < 4; nf++) {
                    int col = n0 + nf * 8 + tq * 2;
                    float ba = s_b1[col], bb2 = s_b1[col + 1];
                    float wa = s_w2[col], wb = s_w2[col + 1];
                    s0 = fmaf(fmaxf(c[mt][nf][0] + ba, 0.0f), wa, s0);
                    s0 = fmaf(fmaxf(c[mt][nf][1] + bb2, 0.0f), wb, s0);
                    s1 = fmaf(fmaxf(c[mt][nf][2] + ba, 0.0f), wa, s1);
                    s1 = fmaf(fmaxf(c[mt][nf][3] + bb2, 0.0f), wb, s1);
                }
                s0 += __shfl_xor_sync(0xFFFFFFFF, s0, 1);
                s0 += __shfl_xor_sync(0xFFFFFFFF, s0, 2);
                s1 += __shfl_xor_sync(0xFFFFFFFF, s1, 1);
                s1 += __shfl_xor_sync(0xFFFFFFFF, s1, 2);
                if (tq == 0) {
                    int row = m0 + mt * 16 + q;
                    part[wn * 128 + row] = s0;
                    part[wn * 128 + row + 8] = s1;
                }
            }
        }
        __syncthreads();  // partials ready; all A(t) reads done

        if (tid < TILE_M) {
            long long p = base + tid;
            if (p < P)
                out[p] = part[tid] + part[128 + tid] + part[256 + tid] +
                         part[384 + tid] + b2v;
        }
        // next iteration's STS targets SM_AH (disjoint from part[]); the
        // loop-top sync orders STS(t+1) vs this iteration's part[] reads.
    }
}

// ---------------- launch ----------------
extern "C" void kernel_launch(void* const* d_in, const int* in_sizes, int n_in,
                              void* d_out, int out_size) {
    const float* g1 = (const float*)d_in[0];
    const float* g2 = (const float*)d_in[1];
    const void* il = d_in[2];
    const void* ir = d_in[3];
    const float* W1 = (const float*)d_in[4];
    const float* b1 = (const float*)d_in[5];
    const float* W2 = (const float*)d_in[6];
    const float* b2 = (const float*)d_in[7];
    long long P = (long long)in_sizes[2];
    long long Nn = (long long)in_sizes[0] / DHALF;

    pip_prep<<<(ED * ED + 255) / 256, 256>>>(W1, il, P, Nn);

    cudaFuncSetAttribute(pip_main, cudaFuncAttributeMaxDynamicSharedMemorySize, SMEM_BYTES);
    int nsm = 148;
    cudaDeviceGetAttribute(&nsm, cudaDevAttrMultiProcessorCount, 0);
    long long nTiles = (P + TILE_M - 1) / TILE_M;
    int grid = (nTiles < (long long)nsm) ? (int)nTiles : nsm;

    pip_main<<<grid, THREADS, SMEM_BYTES>>>(g1, g2, il, ir, b1, W2, b2,
                                            (float*)d_out, P, Nn);
}

// round 13
// speedup vs baseline: 1.5536x; 1.5536x over previous
#include <cuda_runtime.h>
#include <cuda_fp16.h>
#include <stdint.h>

#define ED 128
#define DHALF 64
#define TILE_M 128
#define THREADS 512
#define ROWB 272   // fp16 row stride in bytes (136 halfs) -> conflict-free ldmatrix

// ---------------- device globals ----------------
__device__ __half g_W1h[ED * ED];
__device__ int g_idx64;

// ---------------- helpers ----------------
__device__ __forceinline__ uint32_t smem_u32(const void* p) {
    uint32_t a;
    asm("{ .reg .u64 t; cvta.to.shared.u64 t, %1; cvt.u32.u64 %0, t; }" : "=r"(a) : "l"(p));
    return a;
}
__device__ __forceinline__ void ldsm_x4(uint32_t* r, uint32_t addr) {
    asm volatile("ldmatrix.sync.aligned.m8n8.x4.shared.b16 {%0,%1,%2,%3}, [%4];"
                 : "=r"(r[0]), "=r"(r[1]), "=r"(r[2]), "=r"(r[3]) : "r"(addr));
}
__device__ __forceinline__ void mma16816(float* c, const uint32_t* a, uint32_t b0, uint32_t b1) {
    asm volatile("mma.sync.aligned.m16n8k16.row.col.f32.f16.f16.f32 "
                 "{%0,%1,%2,%3}, {%4,%5,%6,%7}, {%8,%9}, {%0,%1,%2,%3};"
                 : "+f"(c[0]), "+f"(c[1]), "+f"(c[2]), "+f"(c[3])
                 : "r"(a[0]), "r"(a[1]), "r"(a[2]), "r"(a[3]), "r"(b0), "r"(b1));
}

// smem layout (bytes)
#define SM_PART 0                        // float[4][128]
#define SM_B1   2048                     // float[128]
#define SM_W2   2560                     // float[128]
#define SM_BH   3072                     // 128 rows x ROWB
#define SM_AH   (SM_BH + ED * ROWB)      // 128 rows x ROWB
#define SMEM_BYTES (SM_AH + TILE_M * ROWB)

// ---------------- prep: W1 -> fp16; sniff idx dtype ----------------
__global__ void pip_prep(const float* __restrict__ W1, const void* __restrict__ idxl,
                         long long P, long long Nnodes) {
    int i = blockIdx.x * blockDim.x + threadIdx.x;
    if (i < ED * ED) g_W1h[i] = __float2half_rn(W1[i]);
    if (blockIdx.x == 0 && threadIdx.x == 0) {
        const unsigned long long* p64 = (const unsigned long long*)idxl;
        long long n = 512;
        if (2 * n > P) n = P / 2;
        int ok = 1;
        for (long long k = 0; k < n; k++)
            if (p64[k] >= (unsigned long long)Nnodes) { ok = 0; break; }
        g_idx64 = ok;
    }
}

// ---------------- main persistent kernel ----------------
extern "C" __global__ void __launch_bounds__(THREADS, 1)
pip_main(const float* __restrict__ g1, const float* __restrict__ g2,
         const void* __restrict__ idxl, const void* __restrict__ idxr,
         const float* __restrict__ b1, const float* __restrict__ W2,
         const float* __restrict__ b2, float* __restrict__ out,
         long long P, long long Nnodes) {
    extern __shared__ char smem[];
    const uint32_t sb = smem_u32(smem);
    const int tid = threadIdx.x;
    const int wid = tid >> 5;
    const int lid = tid & 31;
    const int is64 = g_idx64;

    // ---- stage b1 / W2 / W1h(B tile, resident all kernel) ----
    for (int i = tid; i < ED; i += THREADS) {
        ((float*)(smem + SM_B1))[i] = b1[i];
        ((float*)(smem + SM_W2))[i] = W2[i];
    }
    for (int i = tid; i < ED * 32; i += THREADS) {  // uint2 = 4 halfs
        int n = i >> 5, kq = i & 31;
        *(uint2*)(smem + SM_BH + n * ROWB + kq * 8) = ((const uint2*)g_W1h)[i];
    }
    __syncthreads();

    // warp tiling: 4m x 4n, warp tile m32 x n32
    const int m0 = (wid >> 2) * 32;
    const int n0 = (wid & 3) * 32;
    const int a_row = (lid & 7) + ((lid >> 3) & 1) * 8;
    const int a_kad = ((lid >> 4) & 1) * 8;
    const int b_row = (lid & 7) + ((lid >> 4) & 1) * 8;
    const int b_kad = ((lid >> 3) & 1) * 8;

    // gather role (coalesced): warp w owns tile rows [8w, 8w+8).
    // lanes 0-15 read left table, 16-31 right table; lane j = float4 j of the row.
    // idx prefetch: lane (sslot*16 + i) holds the byte offset for row (8w + i).
    const int sslot = (lid >> 4) & 1;
    const int j = lid & 15;
    const int idxlane = lid & 7;
    const void* isrc = sslot ? idxr : idxl;
    const float* gsrc = sslot ? g2 : g1;

    const float b2v = b2[0];
    const long long nTiles = (P + TILE_M - 1) / TILE_M;
    const long long grid = gridDim.x;
    float* part = (float*)(smem + SM_PART);
    const float* s_b1 = (const float*)(smem + SM_B1);
    const float* s_w2 = (const float*)(smem + SM_W2);

    long long t = blockIdx.x;
    float4 v[8];          // gathered raw fp32 (consumed only next iteration)
    uint32_t myoff = 0;   // prefetched byte offset for tile t+grid

    // ---- prologue: idx(t) -> gather(t) -> prefetch idx(t+grid) ----
    if (t < nTiles) {
        long long p = t * TILE_M + wid * 8 + idxlane;
        if (p >= P) p = 0;
        long long gi = is64 ? ((const long long*)isrc)[p]
                            : (long long)((const int*)isrc)[p];
        myoff = (uint32_t)gi * (uint32_t)(DHALF * 4);
#pragma unroll
        for (int i = 0; i < 8; i++) {
            uint32_t off = __shfl_sync(0xFFFFFFFFu, myoff, (sslot << 4) + i);
            v[i] = *(const float4*)((const char*)gsrc + off + j * 16);
        }
        long long t2 = t + grid;
        if (t2 < nTiles) {
            long long p2 = t2 * TILE_M + wid * 8 + idxlane;
            if (p2 >= P) p2 = 0;
            long long gi2 = is64 ? ((const long long*)isrc)[p2]
                                 : (long long)((const int*)isrc)[p2];
            myoff = (uint32_t)gi2 * (uint32_t)(DHALF * 4);
        }
    }

    for (; t < nTiles; t += grid) {
        const long long base = t * TILE_M;

        // ---- STS: convert v (fp32) -> fp16 A tile ----
        {
            const uint32_t abase = (uint32_t)(wid * 8 * ROWB + sslot * 128 + j * 8);
#pragma unroll
            for (int i = 0; i < 8; i++) {
                __half2 h01 = __floats2half2_rn(v[i].x, v[i].y);
                __half2 h23 = __floats2half2_rn(v[i].z, v[i].w);
                uint2 w;
                w.x = *(uint32_t*)&h01; w.y = *(uint32_t*)&h23;
                *(uint2*)(smem + SM_AH + abase + i * ROWB) = w;
            }
        }
        __syncthreads();  // A(t) ready

        // ---- issue next-tile gather from prefetched offsets (no idx chain) ----
        const long long tn = t + grid;
        if (tn < nTiles) {
#pragma unroll
            for (int i = 0; i < 8; i++) {
                uint32_t off = __shfl_sync(0xFFFFFFFFu, myoff, (sslot << 4) + i);
                v[i] = *(const float4*)((const char*)gsrc + off + j * 16);
            }
            long long t2 = tn + grid;
            if (t2 < nTiles) {
                long long p2 = t2 * TILE_M + wid * 8 + idxlane;
                if (p2 >= P) p2 = 0;
                long long gi2 = is64 ? ((const long long*)isrc)[p2]
                                     : (long long)((const int*)isrc)[p2];
                myoff = (uint32_t)gi2 * (uint32_t)(DHALF * 4);
            }
        }

        // ---- GEMM: c = A * W1h^T ----
        float c[2][4][4];
#pragma unroll
        for (int mt = 0; mt < 2; mt++)
#pragma unroll
            for (int nf = 0; nf < 4; nf++)
#pragma unroll
                for (int jj = 0; jj < 4; jj++) c[mt][nf][jj] = 0.0f;

#pragma unroll
        for (int ks = 0; ks < 8; ks++) {
            uint32_t ah[2][4], bh[2][4];
#pragma unroll
            for (int mt = 0; mt < 2; mt++) {
                uint32_t ao = (uint32_t)((m0 + mt * 16 + a_row) * ROWB +
                                         (ks * 16 + a_kad) * 2);
                ldsm_x4(ah[mt], sb + SM_AH + ao);
            }
#pragma unroll
            for (int nq = 0; nq < 2; nq++) {
                uint32_t bo = (uint32_t)((n0 + nq * 16 + b_row) * ROWB +
                                         (ks * 16 + b_kad) * 2);
                ldsm_x4(bh[nq], sb + SM_BH + bo);
            }
#pragma unroll
            for (int mt = 0; mt < 2; mt++)
#pragma unroll
                for (int nq = 0; nq < 2; nq++)
#pragma unroll
                    for (int f = 0; f < 2; f++)
                        mma16816(c[mt][nq * 2 + f], ah[mt],
                                 bh[nq][2 * f], bh[nq][2 * f + 1]);
        }

        // ---- epilogue: bias + relu + dot(W2) partials ----
        {
            const int tq = lid & 3;
            const int q = lid >> 2;
            const int wn = wid & 3;
#pragma unroll
            for (int mt = 0; mt < 2; mt++) {
                float s0 = 0.0f, s1 = 0.0f;
#pragma unroll
                for (int nf = 0; nf < 4; nf++) {
                    int col = n0 + nf * 8 + tq * 2;
                    float ba = s_b1[col], bb2 = s_b1[col + 1];
                    float wa = s_w2[col], wb = s_w2[col + 1];
                    s0 = fmaf(fmaxf(c[mt][nf][0] + ba, 0.0f), wa, s0);
                    s0 = fmaf(fmaxf(c[mt][nf][1] + bb2, 0.0f), wb, s0);
                    s1 = fmaf(fmaxf(c[mt][nf][2] + ba, 0.0f), wa, s1);
                    s1 = fmaf(fmaxf(c[mt][nf][3] + bb2, 0.0f), wb, s1);
                }
                s0 += __shfl_xor_sync(0xFFFFFFFF, s0, 1);
                s0 += __shfl_xor_sync(0xFFFFFFFF, s0, 2);
                s1 += __shfl_xor_sync(0xFFFFFFFF, s1, 1);
                s1 += __shfl_xor_sync(0xFFFFFFFF, s1, 2);
                if (tq == 0) {
                    int row = m0 + mt * 16 + q;
                    part[wn * 128 + row] = s0;
                    part[wn * 128 + row + 8] = s1;
                }
            }
        }
        __syncthreads();  // partials ready; all A(t) reads done

        if (tid < TILE_M) {
            long long p = base + tid;
            if (p < P)
                out[p] = part[tid] + part[128 + tid] + part[256 + tid] +
                         part[384 + tid] + b2v;
        }
        // next iteration's STS targets SM_AH (disjoint from part[]); the
        // loop-top sync orders STS(t+1) vs this iteration's part[] reads.
    }
}

// ---------------- launch ----------------
extern "C" void kernel_launch(void* const* d_in, const int* in_sizes, int n_in,
                              void* d_out, int out_size) {
    const float* g1 = (const float*)d_in[0];
    const float* g2 = (const float*)d_in[1];
    const void* il = d_in[2];
    const void* ir = d_in[3];
    const float* W1 = (const float*)d_in[4];
    const float* b1 = (const float*)d_in[5];
    const float* W2 = (const float*)d_in[6];
    const float* b2 = (const float*)d_in[7];
    long long P = (long long)in_sizes[2];
    long long Nn = (long long)in_sizes[0] / DHALF;

    pip_prep<<<(ED * ED + 255) / 256, 256>>>(W1, il, P, Nn);

    cudaFuncSetAttribute(pip_main, cudaFuncAttributeMaxDynamicSharedMemorySize, SMEM_BYTES);
    int nsm = 148;
    cudaDeviceGetAttribute(&nsm, cudaDevAttrMultiProcessorCount, 0);
    long long nTiles = (P + TILE_M - 1) / TILE_M;
    int grid = (nTiles < (long long)nsm) ? (int)nTiles : nsm;

    pip_main<<<grid, THREADS, SMEM_BYTES>>>(g1, g2, il, ir, b1, W2, b2,
                                            (float*)d_out, P, Nn);
}